// round 12
// baseline (speedup 1.0000x reference)
#include <cuda_runtime.h>
#include <cuda_bf16.h>

// B=16, C=128, H=W=224, KS=3, STRIDE=2, ALPHA=16 -> h[z] = -(z/t)^16; Ho=Wo=111.
#define B_  16
#define C_  128
#define H_  224
#define W_  224
#define HO_ 111
#define WO_ 111
#define TR  4                        // output rows per thread
#define NROWS (2*TR + 1)             // 9 input rows

__global__ __launch_bounds__(64, 24)
void lfp_kernel(const float* __restrict__ f,
                const float* __restrict__ t,
                float* __restrict__ out)
{
    __shared__ float xrow[NROWS];                // col-128 patch (warp1 lane0 -> warp0 lane31)

    const int tid = threadIdx.x;                 // 0..63
    const int k   = (tid < 56) ? tid : 55;       // float4 index within row (clamped)
    const int bc  = blockIdx.y;                  // b*C + c
    const int c   = bc & (C_ - 1);

    // h0 = 0, h1 = -(1/t)^16, h2 = -(2/t)^16
    const float inv = 1.0f / __ldg(t + c);
    const float x2  = inv * inv;
    const float x4  = x2 * x2;
    const float x8  = x4 * x4;
    const float x16 = x8 * x8;
    const float h1  = -x16;
    const float h2  = -65536.0f * x16;

    const float* __restrict__ fb = f + (size_t)bc * (H_ * W_);
    float* __restrict__ ob = out + (size_t)bc * (HO_ * WO_);

    const int i0 = blockIdx.x * TR;              // first output row
    const int r0 = 2 * i0;                       // first input row (always even)

    // ---- Phase 1: issue all 9 row loads upfront (max MLP) ----
    float4 A[NROWS];
    #pragma unroll
    for (int r = 0; r < NROWS; ++r) {
        int gr = r0 + r;
        if (gr > H_ - 1) gr = H_ - 1;            // clamp; clamped rows never used
        A[r] = ((const float4*)(fb + (size_t)gr * W_))[k];
    }
    // warp1 lane0 (tid 32, k=32) owns col 128 = A[r].x -> publish for warp0 lane31
    if (tid == 32) {
        #pragma unroll
        for (int r = 0; r < NROWS; ++r) xrow[r] = A[r].x;
    }
    __syncthreads();

    // ---- Phase 2: fold each row to ONE value per owned output column ----
    // Row parity fixes the kernel role: even rows = top/bottom, odd rows = middle.
    //   odd  r: v = max(center,      edge + h1)
    //   even r: v = max(center + h1, edge + h2)
    // j = 2k:   center = A.y, edge = max(A.x, A.z)
    // j = 2k+1: center = A.w, edge = max(A.z, nx)   (nx = next thread's A.x)
    const bool patch = (tid == 31);
    float va[NROWS], vb[NROWS];
    #pragma unroll
    for (int r = 0; r < NROWS; ++r) {
        float nx = __shfl_down_sync(0xffffffffu, A[r].x, 1);
        if (patch) nx = xrow[r];
        const float ca = A[r].y;
        const float ea = fmaxf(A[r].x, A[r].z);
        const float cb = A[r].w;
        const float eb = fmaxf(A[r].z, nx);
        if (r & 1) {                             // middle row
            va[r] = fmaxf(ca, ea + h1);
            vb[r] = fmaxf(cb, eb + h1);
        } else {                                 // top/bottom row
            va[r] = fmaxf(ca + h1, ea + h2);
            vb[r] = fmaxf(cb + h1, eb + h2);
        }
    }

    // ---- Phase 3: out[i] = max(v[2ii], v[2ii+1], v[2ii+2]) ----
    const int ja = 2 * k;                        // 0..110
    const int jb = ja + 1;                       // 1..111 (111 predicated off)
    const bool wa = (tid < 56);
    const bool wb = wa && (jb < WO_);

    #pragma unroll
    for (int ii = 0; ii < TR; ++ii) {
        const int i = i0 + ii;
        if (i >= HO_) break;                     // uniform per block
        const int rt = 2 * ii;

        float oa = fmaxf(va[rt + 1], fmaxf(va[rt], va[rt + 2]));
        float obv = fmaxf(vb[rt + 1], fmaxf(vb[rt], vb[rt + 2]));

        float* orow = ob + (size_t)i * WO_;
        if (wa) orow[ja] = oa;
        if (wb) orow[jb] = obv;
    }
}

extern "C" void kernel_launch(void* const* d_in, const int* in_sizes, int n_in,
                              void* d_out, int out_size)
{
    const float* f = (const float*)d_in[0];
    const float* t = (const float*)d_in[1];
    float* out = (float*)d_out;

    dim3 block(64, 1, 1);
    dim3 grid((HO_ + TR - 1) / TR, B_ * C_, 1);   // 28 x 2048
    lfp_kernel<<<grid, block>>>(f, t, out);
}

// round 14
// speedup vs baseline: 1.1131x; 1.1131x over previous
#include <cuda_runtime.h>
#include <cuda_bf16.h>

// B=16, C=128, H=W=224, KS=3, STRIDE=2, ALPHA=16 -> h[z] = -(z/t)^16; Ho=Wo=111.
#define B_  16
#define C_  128
#define H_  224
#define W_  224
#define HO_ 111
#define WO_ 111
#define TR  4                        // output rows per thread
#define NROWS (2*TR + 1)             // 9 input rows

__global__ __launch_bounds__(64)     // NO min-blocks cap: protect the 9-wide load batch
void lfp_kernel(const float* __restrict__ f,
                const float* __restrict__ t,
                float* __restrict__ out)
{
    __shared__ float xrow[NROWS];                // col-128 patch (warp1 lane0 -> warp0 lane31)

    const int tid = threadIdx.x;                 // 0..63
    const int k   = (tid < 56) ? tid : 55;       // float4 index within row (clamped)
    const int bc  = blockIdx.y;                  // b*C + c
    const int c   = bc & (C_ - 1);

    // h0 = 0, h1 = -(1/t)^16, h2 = -(2/t)^16
    const float inv = 1.0f / __ldg(t + c);
    const float x2  = inv * inv;
    const float x4  = x2 * x2;
    const float x8  = x4 * x4;
    const float x16 = x8 * x8;
    const float h1  = -x16;
    const float h2  = -65536.0f * x16;

    const float* __restrict__ fb = f + (size_t)bc * (H_ * W_);
    float* __restrict__ ob = out + (size_t)bc * (HO_ * WO_);

    const int i0 = blockIdx.x * TR;              // first output row
    const int r0 = 2 * i0;                       // first input row (always even)

    // ---- Phase 1: issue all 9 row loads upfront (max MLP_p1) ----
    float4 A[NROWS];
    #pragma unroll
    for (int r = 0; r < NROWS; ++r) {
        int gr = r0 + r;
        if (gr > H_ - 1) gr = H_ - 1;            // clamp; clamped rows never used
        A[r] = ((const float4*)(fb + (size_t)gr * W_))[k];
    }
    // warp1 lane0 (tid 32, k=32) owns col 128 = A[r].x -> publish for warp0 lane31
    if (tid == 32) {
        #pragma unroll
        for (int r = 0; r < NROWS; ++r) xrow[r] = A[r].x;
    }
    __syncthreads();

    // ---- Phase 2: fold each row to ONE value per owned output column ----
    // Row parity fixes the kernel role: even rows = top/bottom, odd rows = middle.
    //   odd  r: v = max(center,      edge + h1)
    //   even r: v = max(center + h1, edge + h2)
    // j = 2k:   center = A.y, edge = max(A.x, A.z)
    // j = 2k+1: center = A.w, edge = max(A.z, nx)   (nx = next thread's A.x)
    const bool patch = (tid == 31);
    float va[NROWS], vb[NROWS];
    #pragma unroll
    for (int r = 0; r < NROWS; ++r) {
        float nx = __shfl_down_sync(0xffffffffu, A[r].x, 1);
        if (patch) nx = xrow[r];
        const float ca = A[r].y;
        const float ea = fmaxf(A[r].x, A[r].z);
        const float cb = A[r].w;
        const float eb = fmaxf(A[r].z, nx);
        if (r & 1) {                             // middle row
            va[r] = fmaxf(ca, ea + h1);
            vb[r] = fmaxf(cb, eb + h1);
        } else {                                 // top/bottom row
            va[r] = fmaxf(ca + h1, ea + h2);
            vb[r] = fmaxf(cb + h1, eb + h2);
        }
    }

    // ---- Phase 3: out[i] = max(v[2ii], v[2ii+1], v[2ii+2]) ----
    const int ja = 2 * k;                        // 0..110
    const int jb = ja + 1;                       // 1..111 (111 predicated off)
    const bool wa = (tid < 56);
    const bool wb = wa && (jb < WO_);

    #pragma unroll
    for (int ii = 0; ii < TR; ++ii) {
        const int i = i0 + ii;
        if (i >= HO_) break;                     // uniform per block
        const int rt = 2 * ii;

        float oa  = fmaxf(va[rt + 1], fmaxf(va[rt], va[rt + 2]));
        float obv = fmaxf(vb[rt + 1], fmaxf(vb[rt], vb[rt + 2]));

        float* orow = ob + (size_t)i * WO_;
        if (wa) orow[ja] = oa;
        if (wb) orow[jb] = obv;
    }
}

extern "C" void kernel_launch(void* const* d_in, const int* in_sizes, int n_in,
                              void* d_out, int out_size)
{
    const float* f = (const float*)d_in[0];
    const float* t = (const float*)d_in[1];
    float* out = (float*)d_out;

    dim3 block(64, 1, 1);
    dim3 grid((HO_ + TR - 1) / TR, B_ * C_, 1);   // 28 x 2048
    lfp_kernel<<<grid, block>>>(f, t, out);
}